// round 12
// baseline (speedup 1.0000x reference)
#include <cuda_runtime.h>
#include <cstdint>

// DeepSets: out[s,f] = sx_s*W[0,f] + sy_s*W[1,f] + cnt_s*b[f]
// Linearity: segment_sum(xW+b) == segment_sum(x)@W + cnt*b.
//
// ONE persistent kernel, one resident wave (608 CTAs x 256 thr, 4 CTAs/SM):
//  Phase 1: x is streamed via cp.async.bulk (DMA) into a 26KB smem buffer,
//           two mbarrier-phased chunks per CTA. Warps reduce from smem (LDS)
//           — no LDG scoreboard pressure, no register-cache pressure.
//           Boundary attribution: warp-wide lower_bound on ids + smem suffix.
//  Grid barrier: hierarchical arrive (16 groups x 38) -> release generation,
//           all counters monotonic (graph-replay safe).
//  Phase 2: fused epilogue (operands prefetched pre-barrier) -> [4096,64]
//           float4 stores; accumulators reset by their reader threads.

#define FEAT_OUT 64
#define NSEG_MAX 4096
#define K2_CTAS 608
#define K2_THREADS 256
#define CHUNK_F4 1664               // float4 per chunk (26,624 B)
#define NCHUNK 2
#define CTA_F4 (CHUNK_F4 * NCHUNK)  // 3328 f4/CTA; 608*3328 >= 2,000,000
#define WARP_F4 (CHUNK_F4 / 8)      // 208 f4 per warp per chunk
#define NGROUPS 16
#define GROUP_SZ 38

__device__ float    g_px[NSEG_MAX];
__device__ float    g_py[NSEG_MAX];
__device__ int      g_cnt[NSEG_MAX];
__device__ unsigned g_grp[NGROUPS * 32];
__device__ unsigned g_root[32];
__device__ unsigned g_release[32];

__device__ __forceinline__ float warp_sum(float v)
{
    #pragma unroll
    for (int o = 16; o > 0; o >>= 1) v += __shfl_xor_sync(0xFFFFFFFFu, v, o);
    return v;
}

__device__ __forceinline__ int warp_lower_bound(const int* __restrict__ ids,
                                                int lo, int hi, int target)
{
    const int lane = threadIdx.x & 31;
    while (hi > lo) {
        const int m = hi - lo;
        const int p = lo + (int)(((long long)m * (lane + 1)) / 33);
        const int v = __ldg(&ids[p]);
        const unsigned pred = __ballot_sync(0xFFFFFFFFu, v < target);
        const int c = __popc(pred);
        int nlo, nhi;
        if (c == 0)  nlo = lo; else nlo = lo + (int)(((long long)m * c) / 33) + 1;
        if (c == 32) nhi = hi; else nhi = lo + (int)(((long long)m * (c + 1)) / 33);
        lo = nlo; hi = nhi;
    }
    return lo;
}

__device__ __forceinline__ void mbar_wait_parity(uint32_t mbar, uint32_t parity)
{
    asm volatile(
        "{\n\t"
        ".reg .pred P;\n\t"
        "WAIT_%=:\n\t"
        "mbarrier.try_wait.parity.acquire.cta.shared::cta.b64 P, [%0], %1, 0x989680;\n\t"
        "@P bra DONE_%=;\n\t"
        "bra WAIT_%=;\n\t"
        "DONE_%=:\n\t"
        "}"
        :: "r"(mbar), "r"(parity) : "memory");
}

__global__ __launch_bounds__(K2_THREADS, 4)
void deepsets_fused_kernel(const float4* __restrict__ xb,   // [N/2] point pairs
                           const float2* __restrict__ x2,   // [N]
                           const int*    __restrict__ ids,  // [N] sorted
                           const float*  __restrict__ W,    // [2,64]
                           const float*  __restrict__ b,    // [64]
                           float*        __restrict__ out,  // [nseg,64]
                           int N, int NF4, int num_segments)
{
    extern __shared__ float4 s_buf[];            // CHUNK_F4 entries
    __shared__ __align__(8) unsigned long long s_mbar;

    const int lane = threadIdx.x & 31;
    const int wid  = threadIdx.x >> 5;           // 0..7
    const uint32_t mbar_u32  = (uint32_t)__cvta_generic_to_shared(&s_mbar);
    const uint32_t sbuf_u32  = (uint32_t)__cvta_generic_to_shared(s_buf);

    if (threadIdx.x == 0) {
        asm volatile("mbarrier.init.shared.b64 [%0], %1;"
                     :: "r"(mbar_u32), "r"(1u) : "memory");
    }
    __syncthreads();

    // Odd-N straggler point.
    if ((N & 1) && blockIdx.x == 0 && threadIdx.x == 0) {
        const int s = __ldg(&ids[N - 1]);
        const float2 p = __ldg(&x2[N - 1]);
        atomicAdd(&g_px[s], p.x);
        atomicAdd(&g_py[s], p.y);
        atomicAdd(&g_cnt[s], 1);
    }

    const int c_begin = blockIdx.x * CTA_F4;

    for (int r = 0; r < NCHUNK; r++) {
        const int r_begin = c_begin + r * CHUNK_F4;
        const int r_count = min(CHUNK_F4, NF4 - r_begin);
        if (r_count <= 0) break;

        // Issue bulk DMA for this chunk.
        if (threadIdx.x == 0) {
            const uint32_t bytes = (uint32_t)r_count * 16u;
            asm volatile("mbarrier.arrive.expect_tx.shared.b64 _, [%0], %1;"
                         :: "r"(mbar_u32), "r"(bytes) : "memory");
            asm volatile(
                "cp.async.bulk.shared::cta.global.mbarrier::complete_tx::bytes "
                "[%0], [%1], %2, [%3];"
                :: "r"(sbuf_u32), "l"(xb + r_begin), "r"(bytes), "r"(mbar_u32)
                : "memory");
        }

        // Overlap: endpoint id loads (independent of smem) before the wait.
        const int wbeg = r_begin + wid * WARP_F4;
        const int wend = min(wbeg + WARP_F4, NF4);
        int s_lo = 0, s_hi = -1, q0 = 0, pend = 0;
        if (wbeg < wend) {
            q0   = 2 * wbeg;
            pend = 2 * wend;
            s_lo = __ldg(&ids[q0]);
            s_hi = __ldg(&ids[pend - 1]);
        }

        mbar_wait_parity(mbar_u32, (uint32_t)(r & 1));

        if (wbeg < wend) {
            // ---- Totals from smem (LDS.128, conflict-free) ---------------
            float tx = 0.f, ty = 0.f;
            for (int j = wbeg + lane; j < wend; j += 32) {
                const float4 v = s_buf[j - r_begin];
                tx += v.x + v.z;
                ty += v.y + v.w;
            }
            tx = warp_sum(tx); ty = warp_sum(ty);

            // ---- Boundary suffixes (smem re-reads, cheap) ----------------
            const int nseg = s_hi - s_lo + 1;
            float prevSx = tx, prevSy = ty;
            int   prevB  = q0;
            int   searchLo = q0 + 1;

            for (int m = 1; m < nseg; m++) {
                const int Bm = warp_lower_bound(ids, searchLo, pend, s_lo + m);
                searchLo = Bm;
                const int jB = Bm >> 1;           // f4 containing point Bm
                float sx = 0.f, sy = 0.f;
                for (int j = jB + lane; j < wend; j += 32) {
                    const float4 v = s_buf[j - r_begin];
                    sx += v.x + v.z;
                    sy += v.y + v.w;
                }
                sx = warp_sum(sx); sy = warp_sum(sy);
                if (lane == 0) {
                    if (Bm & 1) {
                        // point Bm-1 (even slot of f4 jB) belongs to prev seg
                        const float4 vc = s_buf[jB - r_begin];
                        sx -= vc.x; sy -= vc.y;
                    }
                    atomicAdd(&g_px[s_lo + m - 1],  prevSx - sx);
                    atomicAdd(&g_py[s_lo + m - 1],  prevSy - sy);
                    atomicAdd(&g_cnt[s_lo + m - 1], Bm - prevB);
                    prevSx = sx; prevSy = sy; prevB = Bm;
                }
                prevSx = __shfl_sync(0xFFFFFFFFu, prevSx, 0);
                prevSy = __shfl_sync(0xFFFFFFFFu, prevSy, 0);
                prevB  = __shfl_sync(0xFFFFFFFFu, prevB, 0);
            }
            if (lane == 0) {
                atomicAdd(&g_px[s_hi],  prevSx);
                atomicAdd(&g_py[s_hi],  prevSy);
                atomicAdd(&g_cnt[s_hi], pend - prevB);
            }
        }
        __syncthreads();   // all warps done reading s_buf before next DMA
    }

    // ---- Prefetch epilogue operands (hide under barrier spin) ------------
    const int gid    = blockIdx.x * K2_THREADS + threadIdx.x;
    const int n_out4 = num_segments * (FEAT_OUT / 4);   // 65536
    float4 w0, w1, bb;
    int es = -1;
    if (gid < n_out4) {
        es = gid >> 4;
        const int efq = (gid & 15) << 2;
        w0 = __ldg((const float4*)&W[efq]);
        w1 = __ldg((const float4*)&W[FEAT_OUT + efq]);
        bb = __ldg((const float4*)&b[efq]);
    }

    // -------- Hierarchical grid barrier (monotonic generations) ----------
    __syncthreads();
    if (threadIdx.x == 0) {
        __threadfence();
        const unsigned grp    = blockIdx.x / GROUP_SZ;
        const unsigned ticket = atomicAdd(&g_grp[grp * 32], 1u);
        const unsigned mygen  = ticket / GROUP_SZ;
        if ((ticket % GROUP_SZ) == GROUP_SZ - 1) {
            const unsigned rr = atomicAdd(&g_root[0], 1u);
            if ((rr % NGROUPS) == NGROUPS - 1) {
                atomicAdd(&g_release[0], 1u);
            }
        }
        while (*(volatile unsigned*)&g_release[0] <= mygen)
            __nanosleep(64);
        __threadfence();
    }
    __syncthreads();

    // ---------------- Phase 2: epilogue (float4 per thread) --------------
    if (es >= 0) {
        const float sx  = g_px[es];
        const float sy  = g_py[es];
        const float cnt = (float)g_cnt[es];
        float4 o;
        o.x = fmaf(sx, w0.x, fmaf(sy, w1.x, cnt * bb.x));
        o.y = fmaf(sx, w0.y, fmaf(sy, w1.y, cnt * bb.y));
        o.z = fmaf(sx, w0.z, fmaf(sy, w1.z, cnt * bb.z));
        o.w = fmaf(sx, w0.w, fmaf(sy, w1.w, cnt * bb.w));
        reinterpret_cast<float4*>(out)[gid] = o;
    }
    __syncthreads();

    // Reset by the same threads that read each segment (race-free).
    if (es >= 0) {
        const int rbit = gid & 15;
        if      (rbit == 0) g_px[es]  = 0.f;
        else if (rbit == 1) g_py[es]  = 0.f;
        else if (rbit == 2) g_cnt[es] = 0;
    }
}

extern "C" void kernel_launch(void* const* d_in, const int* in_sizes, int n_in,
                              void* d_out, int out_size)
{
    const float* xf  = (const float*)d_in[0];    // [N,2]
    const int*   ids = (const int*)d_in[1];      // [N] sorted
    const float* W   = (const float*)d_in[2];    // [2,64]
    const float* b   = (const float*)d_in[3];    // [64]
    float* out = (float*)d_out;

    const int N   = in_sizes[0] / 2;
    const int NF4 = N / 2;
    const int num_segments = out_size / FEAT_OUT;   // 4096

    const int smem_bytes = CHUNK_F4 * 16;           // 26,624 B
    cudaFuncSetAttribute(deepsets_fused_kernel,
                         cudaFuncAttributeMaxDynamicSharedMemorySize,
                         smem_bytes);

    deepsets_fused_kernel<<<K2_CTAS, K2_THREADS, smem_bytes>>>(
        (const float4*)xf, (const float2*)xf, ids, W, b, out,
        N, NF4, num_segments);
}